// round 3
// baseline (speedup 1.0000x reference)
#include <cuda_runtime.h>
#include <cstdint>

#define VOCAB 400000
#define DIM 300
#define NQ 512
#define TOPK 5

#define BM 128
#define BN 128
#define BK 12
#define NTILES (VOCAB / BN)   // 3125
#define KITERS (DIM / BK)     // 25

// scratch (device globals: no allocation allowed)
__device__ float g_invnorm[VOCAB];
__device__ float g_Qn[NQ * DIM];
__device__ float g_pv[(size_t)NQ * NTILES * TOPK];   // 32 MB
__device__ int   g_pn[(size_t)NQ * NTILES * TOPK];   // 32 MB

// ---------------------------------------------------------------------------
// Kernel 1: inverse row norms of embedding
// ---------------------------------------------------------------------------
__global__ void invnorm_kernel(const float* __restrict__ E) {
    int warp = (blockIdx.x * blockDim.x + threadIdx.x) >> 5;
    int lane = threadIdx.x & 31;
    if (warp >= VOCAB) return;
    const float4* row = (const float4*)(E + (size_t)warp * DIM);  // 75 float4
    float s = 0.f;
    for (int i = lane; i < DIM / 4; i += 32) {
        float4 v = row[i];
        s += v.x * v.x + v.y * v.y + v.z * v.z + v.w * v.w;
    }
    #pragma unroll
    for (int off = 16; off; off >>= 1) s += __shfl_xor_sync(0xffffffffu, s, off);
    if (lane == 0) g_invnorm[warp] = 1.0f / sqrtf(s);
}

// ---------------------------------------------------------------------------
// Kernel 2: gather + normalize query rows (ids are int32!)
// ---------------------------------------------------------------------------
__global__ void gather_kernel(const float* __restrict__ E,
                              const int* __restrict__ ids) {
    int q = blockIdx.x;
    int id = ids[q];
    float inv = g_invnorm[id];
    const float* src = E + (size_t)id * DIM;
    float* dst = g_Qn + q * DIM;
    for (int k = threadIdx.x; k < DIM; k += blockDim.x) dst[k] = src[k] * inv;
}

// ---------------------------------------------------------------------------
// top-5 helpers (descending; tie -> smaller index, matching lax.top_k)
// ---------------------------------------------------------------------------
__device__ __forceinline__ bool better(float av, int an, float bv, int bn) {
    return (av > bv) || (av == bv && an < bn);
}

__device__ __forceinline__ void ins5(float s, int n, float* v, int* nn) {
    if (better(s, n, v[4], nn[4])) {
        v[4] = s; nn[4] = n;
        #pragma unroll
        for (int j = 4; j > 0; j--) {
            if (better(v[j], nn[j], v[j - 1], nn[j - 1])) {
                float tv = v[j]; v[j] = v[j - 1]; v[j - 1] = tv;
                int tn = nn[j]; nn[j] = nn[j - 1]; nn[j - 1] = tn;
            }
        }
    }
}

__device__ __forceinline__ void merge5(float* v, int* nn,
                                       const float* ov, const int* on) {
    float rv[TOPK]; int rn[TOPK];
    int a = 0, b = 0;
    #pragma unroll
    for (int j = 0; j < TOPK; j++) {
        bool ta = better(v[a], nn[a], ov[b], on[b]);
        rv[j] = ta ? v[a] : ov[b];
        rn[j] = ta ? nn[a] : on[b];
        if (ta) a++; else b++;
    }
    #pragma unroll
    for (int j = 0; j < TOPK; j++) { v[j] = rv[j]; nn[j] = rn[j]; }
}

// ---------------------------------------------------------------------------
// Kernel 3: fused 128x128 SGEMM (f32x2 FFMA2 inner loop) + per-tile top-5
// ---------------------------------------------------------------------------
__global__ __launch_bounds__(256, 2)
void gemm_topk_kernel(const float* __restrict__ E) {
    __shared__ float As[BK][132];
    __shared__ float Bs[BK][132];
    __shared__ float invs[BN];

    const int tid = threadIdx.x;
    const int tx = tid & 15;        // 0..15 -> n micro
    const int ty = tid >> 4;        // 0..15 -> m micro
    const int n0 = blockIdx.x * BN;
    const int m0 = blockIdx.y * BM;

    if (tid < BN) invs[tid] = g_invnorm[n0 + tid];

    // tile-load mapping: 2 threads per row, 6 contiguous floats each
    const int lr = tid >> 1;              // row in tile 0..127
    const int lc = (tid & 1) * 6;         // 0 or 6
    const float* Aptr = g_Qn + (m0 + lr) * DIM + lc;
    const float* Bptr = E + (size_t)(n0 + lr) * DIM + lc;

    float pa[6], pb[6];
    #pragma unroll
    for (int u = 0; u < 6; u++) { pa[u] = Aptr[u]; pb[u] = Bptr[u]; }

    unsigned long long acc[8][4];
    #pragma unroll
    for (int i = 0; i < 8; i++)
        #pragma unroll
        for (int j = 0; j < 4; j++) acc[i][j] = 0ull;

    for (int t = 0; t < KITERS; t++) {
        #pragma unroll
        for (int u = 0; u < 6; u++) {
            As[lc + u][lr] = pa[u];
            Bs[lc + u][lr] = pb[u];
        }
        __syncthreads();

        if (t + 1 < KITERS) {
            const float* An = Aptr + (t + 1) * BK;
            const float* Bn = Bptr + (t + 1) * BK;
            #pragma unroll
            for (int u = 0; u < 6; u++) { pa[u] = An[u]; pb[u] = Bn[u]; }
        }

        #pragma unroll
        for (int k = 0; k < BK; k++) {
            unsigned long long b2[4];
            const unsigned long long* brow = (const unsigned long long*)&Bs[k][0];
            #pragma unroll
            for (int j = 0; j < 4; j++) b2[j] = brow[tx * 4 + j];
            #pragma unroll
            for (int i = 0; i < 8; i++) {
                float a = As[k][ty * 8 + i];
                unsigned long long a2;
                asm("mov.b64 %0, {%1, %1};" : "=l"(a2) : "f"(a));
                #pragma unroll
                for (int j = 0; j < 4; j++) {
                    asm("fma.rn.f32x2 %0, %1, %2, %0;"
                        : "+l"(acc[i][j]) : "l"(a2), "l"(b2[j]));
                }
            }
        }
        __syncthreads();
    }

    // ---- per-row top-5 over this 128-col tile ----
    #pragma unroll 1
    for (int i = 0; i < 8; i++) {
        int m = ty * 8 + i;               // row in tile
        float v[TOPK]; int nn[TOPK];
        #pragma unroll
        for (int j = 0; j < TOPK; j++) { v[j] = -1e30f; nn[j] = 0x7fffffff; }

        #pragma unroll
        for (int j = 0; j < 4; j++) {
            float lo = __uint_as_float((unsigned)(acc[i][j] & 0xffffffffu));
            float hi = __uint_as_float((unsigned)(acc[i][j] >> 32));
            int cl = tx * 8 + 2 * j;
            ins5(lo * invs[cl],     n0 + cl,     v, nn);
            ins5(hi * invs[cl + 1], n0 + cl + 1, v, nn);
        }

        // butterfly merge across the 16 lanes that share this row
        #pragma unroll
        for (int off = 8; off; off >>= 1) {
            float ov[TOPK]; int on[TOPK];
            #pragma unroll
            for (int j = 0; j < TOPK; j++) {
                ov[j] = __shfl_xor_sync(0xffffffffu, v[j], off);
                on[j] = __shfl_xor_sync(0xffffffffu, nn[j], off);
            }
            merge5(v, nn, ov, on);
        }

        if (tx == 0) {
            size_t base = ((size_t)(m0 + m) * NTILES + blockIdx.x) * TOPK;
            #pragma unroll
            for (int j = 0; j < TOPK; j++) {
                g_pv[base + j] = v[j];
                g_pn[base + j] = nn[j];
            }
        }
    }
}

// ---------------------------------------------------------------------------
// Kernel 4: merge per-tile candidates -> final top-5 per query
// ---------------------------------------------------------------------------
__global__ void finalize_kernel(float* __restrict__ out) {
    __shared__ float sv[256][TOPK];
    __shared__ int   sn[256][TOPK];
    int q = blockIdx.x, tid = threadIdx.x;

    float v[TOPK]; int nn[TOPK];
    #pragma unroll
    for (int j = 0; j < TOPK; j++) { v[j] = -1e30f; nn[j] = 0x7fffffff; }

    size_t base = (size_t)q * NTILES * TOPK;
    for (int c = tid; c < NTILES * TOPK; c += 256)
        ins5(g_pv[base + c], g_pn[base + c], v, nn);

    #pragma unroll
    for (int j = 0; j < TOPK; j++) { sv[tid][j] = v[j]; sn[tid][j] = nn[j]; }
    __syncthreads();

    for (int s = 128; s > 0; s >>= 1) {
        if (tid < s) {
            float ov[TOPK]; int on[TOPK];
            #pragma unroll
            for (int j = 0; j < TOPK; j++) {
                v[j] = sv[tid][j]; nn[j] = sn[tid][j];
                ov[j] = sv[tid + s][j]; on[j] = sn[tid + s][j];
            }
            merge5(v, nn, ov, on);
            #pragma unroll
            for (int j = 0; j < TOPK; j++) { sv[tid][j] = v[j]; sn[tid][j] = nn[j]; }
        }
        __syncthreads();
    }

    if (tid == 0) {
        #pragma unroll
        for (int j = 0; j < TOPK; j++) {
            out[q * TOPK + j] = sv[0][j];
            out[NQ * TOPK + q * TOPK + j] = (float)sn[0][j];
        }
    }
}

// ---------------------------------------------------------------------------
extern "C" void kernel_launch(void* const* d_in, const int* in_sizes, int n_in,
                              void* d_out, int out_size) {
    const float* E = (const float*)d_in[0];
    const int* ids = (const int*)d_in[1];
    float* out = (float*)d_out;

    invnorm_kernel<<<(VOCAB + 7) / 8, 256>>>(E);
    gather_kernel<<<NQ, 128>>>(E, ids);
    dim3 grid(NTILES, NQ / BM);
    gemm_topk_kernel<<<grid, 256>>>(E);
    finalize_kernel<<<NQ, 256>>>(out);
}

// round 6
// speedup vs baseline: 1.9855x; 1.9855x over previous
#include <cuda_runtime.h>
#include <cuda_bf16.h>
#include <cstdint>

#define VOCAB 400000
#define DIM 300
#define KP 320                 // padded K (zero-filled 300..319)
#define NQ 512
#define TOPK 5
#define CAND 16
#define BN 64                  // vocab rows per tile
#define NTILES (VOCAB / BN)    // 6250
#define GRIDX 148
#define QGROUP 128
#define NQG (NQ / QGROUP)      // 4

#define APITCH 328             // smem pitch in bf16 elems (656B, conflict-free ldmatrix)
#define ABYTES (QGROUP * APITCH * 2)   // 83968
#define BBYTES (BN * APITCH * 2)       // 41984
#define DPITCH 66
#define DBYTES (QGROUP * DPITCH * 4)   // 33792
#define SMEM_BYTES (1024 + ABYTES + 2 * BBYTES + DBYTES)

// ---------------- device scratch (no allocation allowed) -------------------
__device__ float g_invnorm[VOCAB];
__device__ __align__(128) __nv_bfloat16 g_Ebf[(size_t)VOCAB * KP];   // 256 MB
__device__ __align__(128) __nv_bfloat16 g_Qbf[NQ * KP];
__device__ float g_cv[(size_t)NQ * GRIDX * CAND];
__device__ int   g_ci[(size_t)NQ * GRIDX * CAND];

// ---------------- PTX helpers ----------------------------------------------
__device__ __forceinline__ uint32_t smem_u32(const void* p) {
    uint32_t a;
    asm("{ .reg .u64 t; cvta.to.shared.u64 t, %1; cvt.u32.u64 %0, t; }" : "=r"(a) : "l"(p));
    return a;
}
__device__ __forceinline__ void cpa16(uint32_t dst, const void* src) {
    asm volatile("cp.async.cg.shared.global [%0], [%1], 16;" :: "r"(dst), "l"(src) : "memory");
}
#define CP_COMMIT() asm volatile("cp.async.commit_group;" ::: "memory")
#define CP_WAIT(n)  asm volatile("cp.async.wait_group %0;" :: "n"(n) : "memory")

__device__ __forceinline__ void ldsm_x4(uint32_t* r, uint32_t addr) {
    asm volatile("ldmatrix.sync.aligned.m8n8.x4.shared.b16 {%0,%1,%2,%3}, [%4];"
                 : "=r"(r[0]), "=r"(r[1]), "=r"(r[2]), "=r"(r[3]) : "r"(addr));
}
__device__ __forceinline__ void mma_bf16(float* d, const uint32_t* a, uint32_t b0, uint32_t b1) {
    asm volatile("mma.sync.aligned.m16n8k16.row.col.f32.bf16.bf16.f32 "
                 "{%0,%1,%2,%3}, {%4,%5,%6,%7}, {%8,%9}, {%0,%1,%2,%3};"
                 : "+f"(d[0]), "+f"(d[1]), "+f"(d[2]), "+f"(d[3])
                 : "r"(a[0]), "r"(a[1]), "r"(a[2]), "r"(a[3]), "r"(b0), "r"(b1));
}

// ---------------- ordering helpers -----------------------------------------
__device__ __forceinline__ bool better(float av, int an, float bv, int bn) {
    return (av > bv) || (av == bv && an < bn);
}
__device__ __forceinline__ void ins16(float s, int n, float* v, int* nn) {
    if (better(s, n, v[CAND - 1], nn[CAND - 1])) {
        v[CAND - 1] = s; nn[CAND - 1] = n;
        #pragma unroll
        for (int j = CAND - 1; j > 0; j--) {
            if (better(v[j], nn[j], v[j - 1], nn[j - 1])) {
                float tv = v[j]; v[j] = v[j - 1]; v[j - 1] = tv;
                int tn = nn[j]; nn[j] = nn[j - 1]; nn[j - 1] = tn;
            }
        }
    }
}
__device__ __forceinline__ void merge16(float* v, int* nn, const float* ov, const int* on) {
    float rv[CAND]; int rn[CAND]; int a = 0, b = 0;
    #pragma unroll
    for (int j = 0; j < CAND; j++) {
        bool ta = better(v[a], nn[a], ov[b], on[b]);
        rv[j] = ta ? v[a] : ov[b];
        rn[j] = ta ? nn[a] : on[b];
        if (ta) a++; else b++;
    }
    #pragma unroll
    for (int j = 0; j < CAND; j++) { v[j] = rv[j]; nn[j] = rn[j]; }
}

// ---------------------------------------------------------------------------
// Kernel 1: norms + bf16 normalized table (zero-padded to KP)
// ---------------------------------------------------------------------------
__global__ void prep_kernel(const float* __restrict__ E) {
    int row = blockIdx.x * (blockDim.x >> 5) + (threadIdx.x >> 5);
    int lane = threadIdx.x & 31;
    if (row >= VOCAB) return;
    const float4* r4 = (const float4*)(E + (size_t)row * DIM);
    float s = 0.f;
    for (int i = lane; i < DIM / 4; i += 32) {
        float4 v = r4[i];
        s += v.x * v.x + v.y * v.y + v.z * v.z + v.w * v.w;
    }
    #pragma unroll
    for (int off = 16; off; off >>= 1) s += __shfl_xor_sync(0xffffffffu, s, off);
    float inv = 1.0f / sqrtf(s);
    if (lane == 0) g_invnorm[row] = inv;
    const float* src = E + (size_t)row * DIM;
    __nv_bfloat162* dst = (__nv_bfloat162*)(g_Ebf + (size_t)row * KP);
    for (int j = lane; j < KP / 2; j += 32) {
        int k = 2 * j;
        float a = (k < DIM) ? src[k] * inv : 0.f;
        float b = (k + 1 < DIM) ? src[k + 1] * inv : 0.f;
        dst[j] = __floats2bfloat162_rn(a, b);
    }
}

// ---------------------------------------------------------------------------
// Kernel 2: gather queries -> bf16 normalized, padded
// ---------------------------------------------------------------------------
__global__ void gatherq_kernel(const float* __restrict__ E, const int* __restrict__ ids) {
    int q = blockIdx.x * (blockDim.x >> 5) + (threadIdx.x >> 5);
    int lane = threadIdx.x & 31;
    if (q >= NQ) return;
    int id = ids[q];
    float inv = g_invnorm[id];
    const float* src = E + (size_t)id * DIM;
    __nv_bfloat162* dst = (__nv_bfloat162*)(g_Qbf + q * KP);
    for (int j = lane; j < KP / 2; j += 32) {
        int k = 2 * j;
        float a = (k < DIM) ? src[k] * inv : 0.f;
        float b = (k + 1 < DIM) ? src[k + 1] * inv : 0.f;
        dst[j] = __floats2bfloat162_rn(a, b);
    }
}

// ---------------------------------------------------------------------------
// Kernel 3: bf16 mma.sync GEMM (128 queries x 64 vocab x K=320) + top-16
// 256 threads = 8 warps (4 in M x 2 in N). Warp tile 32x32.
// ---------------------------------------------------------------------------
__global__ __launch_bounds__(256, 1) void gemm_topk_kernel() {
    extern __shared__ char smem[];
    uint32_t sb = smem_u32(smem);
    uint32_t ab = (sb + 1023u) & ~1023u;
    const uint32_t A_S = ab;
    const uint32_t B_S = ab + ABYTES;
    float* Ds = (float*)(smem + (ab - sb) + ABYTES + 2 * BBYTES);

    const int tid = threadIdx.x;
    const int lane = tid & 31;
    const int wid = tid >> 5;
    const int wm = wid & 3;          // 0..3 -> M
    const int wn = wid >> 2;         // 0..1 -> N
    const int qg = blockIdx.x;
    const int bx = blockIdx.y;
    const int nt = (NTILES - bx + GRIDX - 1) / GRIDX;

    // ---- issue A load (queries, stays resident) + first B tile ----
    const __nv_bfloat16* Qsrc = g_Qbf + (size_t)qg * QGROUP * KP;
    for (int i = tid; i < QGROUP * 40; i += 256)
        cpa16(A_S + (i / 40) * (APITCH * 2) + (i % 40) * 16,
              Qsrc + (size_t)(i / 40) * KP + (i % 40) * 8);
    {
        const __nv_bfloat16* src = g_Ebf + (size_t)bx * BN * KP;
        for (int i = tid; i < BN * 40; i += 256)
            cpa16(B_S + (i / 40) * (APITCH * 2) + (i % 40) * 16,
                  src + (size_t)(i / 40) * KP + (i % 40) * 8);
    }
    CP_COMMIT();

    // per-thread ldmatrix base offsets (bytes, add k*2 per k-step)
    uint32_t a_off[2], b_off[2];
    #pragma unroll
    for (int mt = 0; mt < 2; mt++) {
        int r = wm * 32 + mt * 16 + (lane & 7) + ((lane >> 3) & 1) * 8;
        a_off[mt] = A_S + (uint32_t)r * (APITCH * 2) + (uint32_t)(lane >> 4) * 16;
    }
    #pragma unroll
    for (int np = 0; np < 2; np++) {
        int r = wn * 32 + np * 16 + (lane & 7) + (lane >> 4) * 8;
        b_off[np] = (uint32_t)r * (APITCH * 2) + (uint32_t)((lane >> 3) & 1) * 16;
    }

    float cv[CAND]; int ci[CAND];
    #pragma unroll
    for (int j = 0; j < CAND; j++) { cv[j] = -1e30f; ci[j] = 0x7fffffff; }

    for (int t = 0; t < nt; t++) {
        // prefetch next B tile into the other buffer
        if (t + 1 < nt) {
            int vt = bx + (t + 1) * GRIDX;
            uint32_t base = B_S + (uint32_t)((t + 1) & 1) * BBYTES;
            const __nv_bfloat16* src = g_Ebf + (size_t)vt * BN * KP;
            for (int i = tid; i < BN * 40; i += 256)
                cpa16(base + (i / 40) * (APITCH * 2) + (i % 40) * 16,
                      src + (size_t)(i / 40) * KP + (i % 40) * 8);
            CP_COMMIT();
            CP_WAIT(1);
        } else {
            CP_WAIT(0);
        }
        __syncthreads();

        // ---- compute this tile ----
        uint32_t Bbase = B_S + (uint32_t)(t & 1) * BBYTES;
        float d[2][4][4];
        #pragma unroll
        for (int mt = 0; mt < 2; mt++)
            #pragma unroll
            for (int n = 0; n < 4; n++)
                #pragma unroll
                for (int j = 0; j < 4; j++) d[mt][n][j] = 0.f;

        #pragma unroll 5
        for (int k0 = 0; k0 < KP; k0 += 16) {
            uint32_t a[2][4], b[2][4];
            ldsm_x4(a[0], a_off[0] + k0 * 2);
            ldsm_x4(a[1], a_off[1] + k0 * 2);
            ldsm_x4(b[0], Bbase + b_off[0] + k0 * 2);
            ldsm_x4(b[1], Bbase + b_off[1] + k0 * 2);
            #pragma unroll
            for (int mt = 0; mt < 2; mt++) {
                mma_bf16(d[mt][0], a[mt], b[0][0], b[0][1]);
                mma_bf16(d[mt][1], a[mt], b[0][2], b[0][3]);
                mma_bf16(d[mt][2], a[mt], b[1][0], b[1][1]);
                mma_bf16(d[mt][3], a[mt], b[1][2], b[1][3]);
            }
        }

        // ---- stage D to smem ----
        #pragma unroll
        for (int mt = 0; mt < 2; mt++) {
            int r0 = wm * 32 + mt * 16 + (lane >> 2);
            #pragma unroll
            for (int n = 0; n < 4; n++) {
                int c0 = wn * 32 + n * 8 + (lane & 3) * 2;
                *(float2*)&Ds[r0 * DPITCH + c0]       = make_float2(d[mt][n][0], d[mt][n][1]);
                *(float2*)&Ds[(r0 + 8) * DPITCH + c0] = make_float2(d[mt][n][2], d[mt][n][3]);
            }
        }
        __syncthreads();

        // ---- per-query top-16 scan (one thread per query row) ----
        if (tid < QGROUP) {
            const float* row = Ds + tid * DPITCH;
            int vbase = (bx + t * GRIDX) * BN;
            #pragma unroll 8
            for (int c = 0; c < BN; c++) ins16(row[c], vbase + c, cv, ci);
        }
        __syncthreads();
    }

    if (tid < QGROUP) {
        int q = qg * QGROUP + tid;
        size_t base = ((size_t)q * GRIDX + bx) * CAND;
        #pragma unroll
        for (int j = 0; j < CAND; j++) { g_cv[base + j] = cv[j]; g_ci[base + j] = ci[j]; }
    }
}

// ---------------------------------------------------------------------------
// Kernel 4: global approx top-16 -> exact fp32 rescore -> top-5 out
// ---------------------------------------------------------------------------
__global__ void final_kernel(const float* __restrict__ E, const int* __restrict__ ids,
                             float* __restrict__ out) {
    __shared__ float sv[256][CAND];
    __shared__ int   sn[256][CAND];
    __shared__ float ev[CAND];
    int q = blockIdx.x, tid = threadIdx.x;

    float v[CAND]; int nn[CAND];
    #pragma unroll
    for (int j = 0; j < CAND; j++) { v[j] = -1e30f; nn[j] = 0x7fffffff; }
    size_t base = (size_t)q * GRIDX * CAND;
    for (int i = tid; i < GRIDX * CAND; i += 256) ins16(g_cv[base + i], g_ci[base + i], v, nn);
    #pragma unroll
    for (int j = 0; j < CAND; j++) { sv[tid][j] = v[j]; sn[tid][j] = nn[j]; }
    __syncthreads();
    for (int s = 128; s > 0; s >>= 1) {
        if (tid < s) {
            float ov[CAND]; int on[CAND];
            #pragma unroll
            for (int j = 0; j < CAND; j++) {
                v[j] = sv[tid][j]; nn[j] = sn[tid][j];
                ov[j] = sv[tid + s][j]; on[j] = sn[tid + s][j];
            }
            merge16(v, nn, ov, on);
            #pragma unroll
            for (int j = 0; j < CAND; j++) { sv[tid][j] = v[j]; sn[tid][j] = nn[j]; }
        }
        __syncthreads();
    }
    // exact fp32 rescore of the 16 surviving candidates
    int wid = tid >> 5, lane = tid & 31;
    int qid = ids[q];
    float invq = g_invnorm[qid];
    for (int c = wid; c < CAND; c += 8) {
        int vi = sn[0][c];
        float val = -1e30f;
        if (vi >= 0 && vi < VOCAB) {
            const float* a = E + (size_t)qid * DIM;
            const float* b = E + (size_t)vi * DIM;
            float s = 0.f;
            for (int k = lane; k < DIM; k += 32) s += a[k] * b[k];
            #pragma unroll
            for (int off = 16; off; off >>= 1) s += __shfl_xor_sync(0xffffffffu, s, off);
            val = s * invq * g_invnorm[vi];
        }
        if (lane == 0) ev[c] = val;
    }
    __syncthreads();
    if (tid == 0) {
        bool used[CAND];
        #pragma unroll
        for (int j = 0; j < CAND; j++) used[j] = false;
        for (int j = 0; j < TOPK; j++) {
            int best = -1;
            for (int c = 0; c < CAND; c++) {
                if (used[c]) continue;
                if (best < 0 || better(ev[c], sn[0][c], ev[best], sn[0][best])) best = c;
            }
            used[best] = true;
            out[q * TOPK + j] = ev[best];
            out[NQ * TOPK + q * TOPK + j] = (float)sn[0][best];
        }
    }
}

// ---------------------------------------------------------------------------
extern "C" void kernel_launch(void* const* d_in, const int* in_sizes, int n_in,
                              void* d_out, int out_size) {
    const float* E = (const float*)d_in[0];
    const int* ids = (const int*)d_in[1];
    float* out = (float*)d_out;

    cudaFuncSetAttribute(gemm_topk_kernel, cudaFuncAttributeMaxDynamicSharedMemorySize, SMEM_BYTES);

    prep_kernel<<<VOCAB / 8, 256>>>(E);
    gatherq_kernel<<<NQ / 8, 256>>>(E, ids);
    gemm_topk_kernel<<<dim3(NQG, GRIDX), 256, SMEM_BYTES>>>();
    final_kernel<<<NQ, 256>>>(E, ids, out);
}